// round 2
// baseline (speedup 1.0000x reference)
#include <cuda_runtime.h>
#include <cuda_bf16.h>

#define USER_NUM 100000
#define ITEM_NUM 50000
#define N_NODES  150000
#define EMB      64
#define LAYERS   3
#define NNZ      2400000

// ---------------- device scratch (static globals: allocation-free) ----------
__device__ float g_ego [N_NODES * EMB];
__device__ float g_temp[N_NODES * EMB];
__device__ float g_aggT[N_NODES * EMB];
__device__ float g_aggE[N_NODES * EMB];
__device__ float g_acc [N_NODES * EMB];
__device__ int   g_rowptr[N_NODES + 1];
__device__ int   g_cursor[N_NODES];
__device__ int   g_counts[N_NODES];
__device__ int   g_bsums[256];
__device__ int2  g_edges[NNZ];           // .x = col, .y = bits(val)

// ---------------- init: concat embeddings into ego & acc, zero counts ------
__global__ void k_init(const float* __restrict__ u, const float* __restrict__ it) {
    int i = blockIdx.x * blockDim.x + threadIdx.x;
    if (i < USER_NUM * EMB) {
        float v = u[i];
        g_ego[i] = v; g_acc[i] = v;
    } else if (i < N_NODES * EMB) {
        float v = it[i - USER_NUM * EMB];
        g_ego[i] = v; g_acc[i] = v;
    }
    if (i < N_NODES) g_counts[i] = 0;
}

// ---------------- CSR build --------------------------------------------------
__global__ void k_hist(const int* __restrict__ rows) {
    int i = blockIdx.x * blockDim.x + threadIdx.x;
    if (i < NNZ) atomicAdd(&g_counts[rows[i]], 1);
}

// per-block exclusive scan (1024 elems/block); block totals -> g_bsums
__global__ void k_scan_blocks() {
    __shared__ int sm[1024];
    int idx = blockIdx.x * 1024 + threadIdx.x;
    int v = (idx < N_NODES) ? g_counts[idx] : 0;
    sm[threadIdx.x] = v;
    __syncthreads();
    #pragma unroll
    for (int off = 1; off < 1024; off <<= 1) {
        int t = (threadIdx.x >= off) ? sm[threadIdx.x - off] : 0;
        __syncthreads();
        sm[threadIdx.x] += t;
        __syncthreads();
    }
    if (idx < N_NODES) g_rowptr[idx] = sm[threadIdx.x] - v;   // exclusive
    if (threadIdx.x == 1023) g_bsums[blockIdx.x] = sm[1023];
}

__global__ void k_scan_sums(int nb) {
    __shared__ int sm[256];
    int v = (threadIdx.x < nb) ? g_bsums[threadIdx.x] : 0;
    sm[threadIdx.x] = v;
    __syncthreads();
    #pragma unroll
    for (int off = 1; off < 256; off <<= 1) {
        int t = (threadIdx.x >= off) ? sm[threadIdx.x - off] : 0;
        __syncthreads();
        sm[threadIdx.x] += t;
        __syncthreads();
    }
    if (threadIdx.x < nb) g_bsums[threadIdx.x] = sm[threadIdx.x] - v;  // exclusive
}

__global__ void k_add_offsets() {
    int idx = blockIdx.x * 1024 + threadIdx.x;
    if (idx < N_NODES) {
        int r = g_rowptr[idx] + g_bsums[blockIdx.x];
        g_rowptr[idx] = r;
        g_cursor[idx] = r;
    }
    if (idx == 0) g_rowptr[N_NODES] = NNZ;
}

__global__ void k_scatter(const int* __restrict__ rows, const int* __restrict__ cols,
                          const float* __restrict__ vals) {
    int i = blockIdx.x * blockDim.x + threadIdx.x;
    if (i < NNZ) {
        int r = rows[i];
        int p = atomicAdd(&g_cursor[r], 1);
        g_edges[p] = make_int2(cols[i], __float_as_int(vals[i]));
    }
}

// ---------------- temp = ego @ w1[k]  (warp-per-row) -----------------------
__global__ void k_gemm_w1(const float* __restrict__ w) {
    __shared__ float sw[64 * 64];   // packed: float2 [(k*32 + j%32)] = (w[k][j], w[k][j+32])
    for (int i = threadIdx.x; i < 4096; i += blockDim.x) {
        int k = i >> 6, j = i & 63;
        sw[(k * 32 + (j & 31)) * 2 + (j >> 5)] = w[i];
    }
    __syncthreads();
    const float2* swp = (const float2*)sw;
    int lane = threadIdx.x & 31;
    int wid = (blockIdx.x * blockDim.x + threadIdx.x) >> 5;
    int nw  = (gridDim.x * blockDim.x) >> 5;
    for (int row = wid; row < N_NODES; row += nw) {
        float x0 = g_ego[row * 64 + lane];
        float x1 = g_ego[row * 64 + lane + 32];
        float o0 = 0.f, o1 = 0.f;
        #pragma unroll
        for (int k = 0; k < 32; k++) {
            float z = __shfl_sync(0xffffffffu, x0, k);
            float2 wv = swp[k * 32 + lane];
            o0 += z * wv.x; o1 += z * wv.y;
        }
        #pragma unroll
        for (int k = 0; k < 32; k++) {
            float z = __shfl_sync(0xffffffffu, x1, k);
            float2 wv = swp[(k + 32) * 32 + lane];
            o0 += z * wv.x; o1 += z * wv.y;
        }
        g_temp[row * 64 + lane]      = o0;
        g_temp[row * 64 + lane + 32] = o1;
    }
}

// ---------------- dual SpMM: aggT = A@temp, aggE = A@ego (row-per-warp) ----
__global__ void k_spmm_dual() {
    int gw = (blockIdx.x * blockDim.x + threadIdx.x) >> 5;
    if (gw >= N_NODES) return;
    int lane = threadIdx.x & 31;
    int half = lane >> 4;       // 0/1 — two edges in flight per warp
    int hl   = lane & 15;       // float4 slot within row (16*4 = 64 floats)
    int s = g_rowptr[gw], e = g_rowptr[gw + 1];
    float4 aT = make_float4(0.f, 0.f, 0.f, 0.f);
    float4 aE = make_float4(0.f, 0.f, 0.f, 0.f);
    for (int i = s + half; i < e; i += 2) {
        int2 ed = g_edges[i];
        float v = __int_as_float(ed.y);
        const float4* tp = (const float4*)(g_temp + ed.x * 64);
        const float4* ep = (const float4*)(g_ego  + ed.x * 64);
        float4 t = tp[hl];
        float4 x = ep[hl];
        aT.x += v * t.x; aT.y += v * t.y; aT.z += v * t.z; aT.w += v * t.w;
        aE.x += v * x.x; aE.y += v * x.y; aE.z += v * x.z; aE.w += v * x.w;
    }
    aT.x += __shfl_xor_sync(0xffffffffu, aT.x, 16);
    aT.y += __shfl_xor_sync(0xffffffffu, aT.y, 16);
    aT.z += __shfl_xor_sync(0xffffffffu, aT.z, 16);
    aT.w += __shfl_xor_sync(0xffffffffu, aT.w, 16);
    aE.x += __shfl_xor_sync(0xffffffffu, aE.x, 16);
    aE.y += __shfl_xor_sync(0xffffffffu, aE.y, 16);
    aE.z += __shfl_xor_sync(0xffffffffu, aE.z, 16);
    aE.w += __shfl_xor_sync(0xffffffffu, aE.w, 16);
    if (half == 0) {
        ((float4*)(g_aggT + gw * 64))[hl] = aT;
        ((float4*)(g_aggE + gw * 64))[hl] = aE;
    }
}

// ------------- epilogue: ego = lrelu(aggT + temp + (aggE*ego)@w2); acc += --
__global__ void k_epilogue(const float* __restrict__ w, float* __restrict__ dout,
                           int final_layer) {
    __shared__ float sw[64 * 64];
    for (int i = threadIdx.x; i < 4096; i += blockDim.x) {
        int k = i >> 6, j = i & 63;
        sw[(k * 32 + (j & 31)) * 2 + (j >> 5)] = w[i];
    }
    __syncthreads();
    const float2* swp = (const float2*)sw;
    int lane = threadIdx.x & 31;
    int wid = (blockIdx.x * blockDim.x + threadIdx.x) >> 5;
    int nw  = (gridDim.x * blockDim.x) >> 5;
    for (int row = wid; row < N_NODES; row += nw) {
        int base = row * 64;
        float e0 = g_ego[base + lane];
        float e1 = g_ego[base + lane + 32];
        float a0 = g_aggE[base + lane]      * e0;   // z = agg_ego * ego
        float a1 = g_aggE[base + lane + 32] * e1;
        float o0 = g_aggT[base + lane]      + g_temp[base + lane];
        float o1 = g_aggT[base + lane + 32] + g_temp[base + lane + 32];
        #pragma unroll
        for (int k = 0; k < 32; k++) {
            float z = __shfl_sync(0xffffffffu, a0, k);
            float2 wv = swp[k * 32 + lane];
            o0 += z * wv.x; o1 += z * wv.y;
        }
        #pragma unroll
        for (int k = 0; k < 32; k++) {
            float z = __shfl_sync(0xffffffffu, a1, k);
            float2 wv = swp[(k + 32) * 32 + lane];
            o0 += z * wv.x; o1 += z * wv.y;
        }
        o0 = (o0 > 0.f) ? o0 : 0.01f * o0;
        o1 = (o1 > 0.f) ? o1 : 0.01f * o1;
        if (final_layer) {
            dout[base + lane]      = (g_acc[base + lane]      + o0) * 0.25f;
            dout[base + lane + 32] = (g_acc[base + lane + 32] + o1) * 0.25f;
        } else {
            g_ego[base + lane]      = o0;
            g_ego[base + lane + 32] = o1;
            g_acc[base + lane]      += o0;
            g_acc[base + lane + 32] += o1;
        }
    }
}

// ---------------- launch -----------------------------------------------------
extern "C" void kernel_launch(void* const* d_in, const int* in_sizes, int n_in,
                              void* d_out, int out_size) {
    const float* user_emb = (const float*)d_in[0];
    const float* item_emb = (const float*)d_in[1];
    const float* w1       = (const float*)d_in[2];   // [3,64,64]
    const float* w2       = (const float*)d_in[3];   // [3,64,64]
    const float* adj_vals = (const float*)d_in[4];
    const int*   adj_rows = (const int*)d_in[5];
    const int*   adj_cols = (const int*)d_in[6];
    float* dout = (float*)d_out;

    const int NB_SCAN = (N_NODES + 1023) / 1024;     // 147

    k_init<<<(N_NODES * EMB + 255) / 256, 256>>>(user_emb, item_emb);
    k_hist<<<(NNZ + 255) / 256, 256>>>(adj_rows);
    k_scan_blocks<<<NB_SCAN, 1024>>>();
    k_scan_sums<<<1, 256>>>(NB_SCAN);
    k_add_offsets<<<NB_SCAN, 1024>>>();
    k_scatter<<<(NNZ + 255) / 256, 256>>>(adj_rows, adj_cols, adj_vals);

    const int GEMM_BLOCKS = 1184;                    // 8 * 148 SMs, grid-stride
    const int SPMM_BLOCKS = (N_NODES * 32 + 255) / 256;   // warp per row

    for (int k = 0; k < LAYERS; k++) {
        k_gemm_w1<<<GEMM_BLOCKS, 256>>>(w1 + k * EMB * EMB);
        k_spmm_dual<<<SPMM_BLOCKS, 256>>>();
        k_epilogue<<<GEMM_BLOCKS, 256>>>(w2 + k * EMB * EMB, dout, k == LAYERS - 1);
    }
    (void)in_sizes; (void)n_in; (void)out_size;
}

// round 5
// speedup vs baseline: 1.2183x; 1.2183x over previous
#include <cuda_runtime.h>
#include <cuda_bf16.h>

#define USER_NUM 100000
#define ITEM_NUM 50000
#define N_NODES  150000
#define EMB      64
#define LAYERS   3
#define NNZ      2400000

// ---------------- device scratch (static globals: allocation-free) ----------
__device__ float g_ego [N_NODES * EMB];
__device__ float g_aggE[N_NODES * EMB];
__device__ float g_acc [N_NODES * EMB];
__device__ int   g_rowptr[N_NODES + 1];
__device__ int   g_cursor[N_NODES];
__device__ int   g_counts[N_NODES];
__device__ int   g_bsums[256];
__device__ int2  g_edges[NNZ];           // .x = col, .y = bits(val)

// ---------------- init: concat embeddings into ego & acc, zero counts ------
__global__ void k_init(const float* __restrict__ u, const float* __restrict__ it) {
    int i = blockIdx.x * blockDim.x + threadIdx.x;
    if (i < USER_NUM * EMB) {
        float v = u[i];
        g_ego[i] = v; g_acc[i] = v;
    } else if (i < N_NODES * EMB) {
        float v = it[i - USER_NUM * EMB];
        g_ego[i] = v; g_acc[i] = v;
    }
    if (i < N_NODES) g_counts[i] = 0;
}

// ---------------- CSR build --------------------------------------------------
__global__ void k_hist(const int* __restrict__ rows) {
    int i = blockIdx.x * blockDim.x + threadIdx.x;
    if (i < NNZ) atomicAdd(&g_counts[rows[i]], 1);
}

// per-block exclusive scan (1024 elems/block); block totals -> g_bsums
__global__ void k_scan_blocks() {
    __shared__ int sm[1024];
    int idx = blockIdx.x * 1024 + threadIdx.x;
    int v = (idx < N_NODES) ? g_counts[idx] : 0;
    sm[threadIdx.x] = v;
    __syncthreads();
    #pragma unroll
    for (int off = 1; off < 1024; off <<= 1) {
        int t = (threadIdx.x >= off) ? sm[threadIdx.x - off] : 0;
        __syncthreads();
        sm[threadIdx.x] += t;
        __syncthreads();
    }
    if (idx < N_NODES) g_rowptr[idx] = sm[threadIdx.x] - v;   // exclusive
    if (threadIdx.x == 1023) g_bsums[blockIdx.x] = sm[1023];
}

__global__ void k_scan_sums(int nb) {
    __shared__ int sm[256];
    int v = (threadIdx.x < nb) ? g_bsums[threadIdx.x] : 0;
    sm[threadIdx.x] = v;
    __syncthreads();
    #pragma unroll
    for (int off = 1; off < 256; off <<= 1) {
        int t = (threadIdx.x >= off) ? sm[threadIdx.x - off] : 0;
        __syncthreads();
        sm[threadIdx.x] += t;
        __syncthreads();
    }
    if (threadIdx.x < nb) g_bsums[threadIdx.x] = sm[threadIdx.x] - v;  // exclusive
}

__global__ void k_add_offsets() {
    int idx = blockIdx.x * 1024 + threadIdx.x;
    if (idx < N_NODES) {
        int r = g_rowptr[idx] + g_bsums[blockIdx.x];
        g_rowptr[idx] = r;
        g_cursor[idx] = r;
    }
    if (idx == 0) g_rowptr[N_NODES] = NNZ;
}

__global__ void k_scatter(const int* __restrict__ rows, const int* __restrict__ cols,
                          const float* __restrict__ vals) {
    int i = blockIdx.x * blockDim.x + threadIdx.x;
    if (i < NNZ) {
        int r = rows[i];
        int p = atomicAdd(&g_cursor[r], 1);
        g_edges[p] = make_int2(cols[i], __float_as_int(vals[i]));
    }
}

// ---------------- single SpMM: aggE = A @ ego (row-per-warp, 4 edges in flight)
__global__ void k_spmm() {
    int gw = (blockIdx.x * blockDim.x + threadIdx.x) >> 5;
    if (gw >= N_NODES) return;
    int lane = threadIdx.x & 31;
    int q  = lane >> 3;      // 0..3 — four edges in flight per warp
    int ql = lane & 7;       // 8 lanes per edge, 2x float4 each (64 floats)
    int s = g_rowptr[gw], e = g_rowptr[gw + 1];
    float4 a0 = make_float4(0.f, 0.f, 0.f, 0.f);
    float4 a1 = make_float4(0.f, 0.f, 0.f, 0.f);
    for (int i = s + q; i < e; i += 4) {
        int2 ed = g_edges[i];
        float v = __int_as_float(ed.y);
        const float4* ep = (const float4*)(g_ego + ed.x * 64);
        float4 x0 = ep[ql];
        float4 x1 = ep[ql + 8];
        a0.x += v * x0.x; a0.y += v * x0.y; a0.z += v * x0.z; a0.w += v * x0.w;
        a1.x += v * x1.x; a1.y += v * x1.y; a1.z += v * x1.z; a1.w += v * x1.w;
    }
    #pragma unroll
    for (int off = 8; off <= 16; off <<= 1) {
        a0.x += __shfl_xor_sync(0xffffffffu, a0.x, off);
        a0.y += __shfl_xor_sync(0xffffffffu, a0.y, off);
        a0.z += __shfl_xor_sync(0xffffffffu, a0.z, off);
        a0.w += __shfl_xor_sync(0xffffffffu, a0.w, off);
        a1.x += __shfl_xor_sync(0xffffffffu, a1.x, off);
        a1.y += __shfl_xor_sync(0xffffffffu, a1.y, off);
        a1.z += __shfl_xor_sync(0xffffffffu, a1.z, off);
        a1.w += __shfl_xor_sync(0xffffffffu, a1.w, off);
    }
    if (q == 0) {
        ((float4*)(g_aggE + gw * 64))[ql]     = a0;
        ((float4*)(g_aggE + gw * 64))[ql + 8] = a1;
    }
}

// ------------- fused layer: ego' = lrelu((ego+aggE)@w1 + (aggE*ego)@w2) -----
//               acc += ego'   (or final: dout = (acc + ego')*0.25)
__global__ void k_layer(const float* __restrict__ w1, const float* __restrict__ w2,
                        float* __restrict__ dout, int final_layer) {
    __shared__ float sw1[64 * 64];   // packed: [(k*32 + j%32)] -> (w[k][j], w[k][j+32])
    __shared__ float sw2[64 * 64];
    for (int i = threadIdx.x; i < 4096; i += blockDim.x) {
        int k = i >> 6, j = i & 63;
        int p = (k * 32 + (j & 31)) * 2 + (j >> 5);
        sw1[p] = w1[i];
        sw2[p] = w2[i];
    }
    __syncthreads();
    const float2* wp1 = (const float2*)sw1;
    const float2* wp2 = (const float2*)sw2;
    int lane = threadIdx.x & 31;
    int wid = (blockIdx.x * blockDim.x + threadIdx.x) >> 5;
    int nw  = (gridDim.x * blockDim.x) >> 5;
    for (int row = wid; row < N_NODES; row += nw) {
        int base = row * 64;
        float e0 = g_ego[base + lane];
        float e1 = g_ego[base + lane + 32];
        float g0 = g_aggE[base + lane];
        float g1 = g_aggE[base + lane + 32];
        float s0 = e0 + g0, s1 = e1 + g1;     // (ego + aggE) -> @w1
        float z0 = e0 * g0, z1 = e1 * g1;     // (aggE * ego) -> @w2
        float o0 = 0.f, o1 = 0.f;
        #pragma unroll
        for (int k = 0; k < 32; k++) {
            float sv = __shfl_sync(0xffffffffu, s0, k);
            float zv = __shfl_sync(0xffffffffu, z0, k);
            float2 a = wp1[k * 32 + lane];
            float2 b = wp2[k * 32 + lane];
            o0 += sv * a.x + zv * b.x;
            o1 += sv * a.y + zv * b.y;
        }
        #pragma unroll
        for (int k = 0; k < 32; k++) {
            float sv = __shfl_sync(0xffffffffu, s1, k);
            float zv = __shfl_sync(0xffffffffu, z1, k);
            float2 a = wp1[(k + 32) * 32 + lane];
            float2 b = wp2[(k + 32) * 32 + lane];
            o0 += sv * a.x + zv * b.x;
            o1 += sv * a.y + zv * b.y;
        }
        o0 = (o0 > 0.f) ? o0 : 0.01f * o0;
        o1 = (o1 > 0.f) ? o1 : 0.01f * o1;
        if (final_layer) {
            dout[base + lane]      = (g_acc[base + lane]      + o0) * 0.25f;
            dout[base + lane + 32] = (g_acc[base + lane + 32] + o1) * 0.25f;
        } else {
            g_ego[base + lane]      = o0;
            g_ego[base + lane + 32] = o1;
            g_acc[base + lane]      += o0;
            g_acc[base + lane + 32] += o1;
        }
    }
}

// ---------------- launch -----------------------------------------------------
extern "C" void kernel_launch(void* const* d_in, const int* in_sizes, int n_in,
                              void* d_out, int out_size) {
    const float* user_emb = (const float*)d_in[0];
    const float* item_emb = (const float*)d_in[1];
    const float* w1       = (const float*)d_in[2];   // [3,64,64]
    const float* w2       = (const float*)d_in[3];   // [3,64,64]
    const float* adj_vals = (const float*)d_in[4];
    const int*   adj_rows = (const int*)d_in[5];
    const int*   adj_cols = (const int*)d_in[6];
    float* dout = (float*)d_out;

    const int NB_SCAN = (N_NODES + 1023) / 1024;     // 147

    k_init<<<(N_NODES * EMB + 255) / 256, 256>>>(user_emb, item_emb);
    k_hist<<<(NNZ + 255) / 256, 256>>>(adj_rows);
    k_scan_blocks<<<NB_SCAN, 1024>>>();
    k_scan_sums<<<1, 256>>>(NB_SCAN);
    k_add_offsets<<<NB_SCAN, 1024>>>();
    k_scatter<<<(NNZ + 255) / 256, 256>>>(adj_rows, adj_cols, adj_vals);

    const int LAYER_BLOCKS = 1184;                        // grid-stride, 8*148
    const int SPMM_BLOCKS  = (N_NODES * 32 + 255) / 256;  // warp per row

    for (int k = 0; k < LAYERS; k++) {
        k_spmm<<<SPMM_BLOCKS, 256>>>();
        k_layer<<<LAYER_BLOCKS, 256>>>(w1 + k * EMB * EMB, w2 + k * EMB * EMB,
                                       dout, k == LAYERS - 1);
    }
    (void)in_sizes; (void)n_in; (void)out_size;
}

// round 6
// speedup vs baseline: 1.2304x; 1.0099x over previous
#include <cuda_runtime.h>
#include <cuda_bf16.h>

#define USER_NUM 100000
#define ITEM_NUM 50000
#define N_NODES  150000
#define EMB      64
#define LAYERS   3
#define NNZ      2400000

// ---------------- device scratch (static globals: allocation-free) ----------
__device__ float g_egoA[N_NODES * EMB];
__device__ float g_egoB[N_NODES * EMB];
__device__ float g_acc [N_NODES * EMB];
__device__ int   g_rowptr[N_NODES + 1];
__device__ int   g_cursor[N_NODES];
__device__ int   g_counts[N_NODES];
__device__ int   g_bsums[256];
__device__ int2  g_edges[NNZ];           // .x = col, .y = bits(val)

// ------------- init embeddings + histogram rows in one kernel ---------------
__global__ void k_init_hist(const float* __restrict__ u, const float* __restrict__ it,
                            const int* __restrict__ rows) {
    int i = blockIdx.x * blockDim.x + threadIdx.x;
    if (i < USER_NUM * EMB) {
        float v = u[i];
        g_egoA[i] = v; g_acc[i] = v;
    } else if (i < N_NODES * EMB) {
        float v = it[i - USER_NUM * EMB];
        g_egoA[i] = v; g_acc[i] = v;
    }
    if (i < N_NODES) g_counts[i] = 0;
}

__global__ void k_hist(const int* __restrict__ rows) {
    int i = blockIdx.x * blockDim.x + threadIdx.x;
    if (i < NNZ) atomicAdd(&g_counts[rows[i]], 1);
}

// per-block exclusive scan (1024 elems/block); block totals -> g_bsums
__global__ void k_scan_blocks() {
    __shared__ int sm[1024];
    int idx = blockIdx.x * 1024 + threadIdx.x;
    int v = (idx < N_NODES) ? g_counts[idx] : 0;
    sm[threadIdx.x] = v;
    __syncthreads();
    #pragma unroll
    for (int off = 1; off < 1024; off <<= 1) {
        int t = (threadIdx.x >= off) ? sm[threadIdx.x - off] : 0;
        __syncthreads();
        sm[threadIdx.x] += t;
        __syncthreads();
    }
    if (idx < N_NODES) g_rowptr[idx] = sm[threadIdx.x] - v;   // exclusive
    if (threadIdx.x == 1023) g_bsums[blockIdx.x] = sm[1023];
}

__global__ void k_scan_sums(int nb) {
    __shared__ int sm[256];
    int v = (threadIdx.x < nb) ? g_bsums[threadIdx.x] : 0;
    sm[threadIdx.x] = v;
    __syncthreads();
    #pragma unroll
    for (int off = 1; off < 256; off <<= 1) {
        int t = (threadIdx.x >= off) ? sm[threadIdx.x - off] : 0;
        __syncthreads();
        sm[threadIdx.x] += t;
        __syncthreads();
    }
    if (threadIdx.x < nb) g_bsums[threadIdx.x] = sm[threadIdx.x] - v;  // exclusive
}

__global__ void k_add_offsets() {
    int idx = blockIdx.x * 1024 + threadIdx.x;
    if (idx < N_NODES) {
        int r = g_rowptr[idx] + g_bsums[blockIdx.x];
        g_rowptr[idx] = r;
        g_cursor[idx] = r;
    }
    if (idx == 0) g_rowptr[N_NODES] = NNZ;
}

__global__ void k_scatter(const int* __restrict__ rows, const int* __restrict__ cols,
                          const float* __restrict__ vals) {
    int i = blockIdx.x * blockDim.x + threadIdx.x;
    if (i < NNZ) {
        int r = rows[i];
        int p = atomicAdd(&g_cursor[r], 1);
        g_edges[p] = make_int2(cols[i], __float_as_int(vals[i]));
    }
}

// ------------- fully fused layer: per row (warp):
//   g = (A @ src)[row]              (gather, lane owns cols lane/lane+32)
//   ego' = lrelu((src_row+g)@w1 + (g*src_row)@w2)
//   acc += ego'  (final: dout = (acc+ego')*0.25)
__global__ void __launch_bounds__(256) k_fused(const float* __restrict__ w1,
                                               const float* __restrict__ w2,
                                               float* __restrict__ dout,
                                               int parity, int final_layer) {
    __shared__ float sw1[64 * 64];   // packed: [(k*32 + j%32)] -> (w[k][j], w[k][j+32])
    __shared__ float sw2[64 * 64];
    for (int i = threadIdx.x; i < 4096; i += blockDim.x) {
        int k = i >> 6, j = i & 63;
        int p = (k * 32 + (j & 31)) * 2 + (j >> 5);
        sw1[p] = w1[i];
        sw2[p] = w2[i];
    }
    __syncthreads();
    const float2* wp1 = (const float2*)sw1;
    const float2* wp2 = (const float2*)sw2;

    const float* __restrict__ src = parity ? g_egoB : g_egoA;
    float* __restrict__ dst       = parity ? g_egoA : g_egoB;

    int lane = threadIdx.x & 31;
    int wid = (blockIdx.x * blockDim.x + threadIdx.x) >> 5;
    int nw  = (gridDim.x * blockDim.x) >> 5;

    for (int row = wid; row < N_NODES; row += nw) {
        int base = row * 64;
        // ---- gather: g = sum_e v_e * src[col_e]  (lane-owned columns) ----
        int s = g_rowptr[row], e = g_rowptr[row + 1];
        float gA0 = 0.f, gA1 = 0.f, gB0 = 0.f, gB1 = 0.f;
        int i = s;
        for (; i + 1 < e; i += 2) {
            int2 e0 = g_edges[i];
            int2 e1 = g_edges[i + 1];
            float v0 = __int_as_float(e0.y);
            float v1 = __int_as_float(e1.y);
            const float* p0 = src + e0.x * 64;
            const float* p1 = src + e1.x * 64;
            float x00 = p0[lane], x01 = p0[lane + 32];
            float x10 = p1[lane], x11 = p1[lane + 32];
            gA0 += v0 * x00; gA1 += v0 * x01;
            gB0 += v1 * x10; gB1 += v1 * x11;
        }
        if (i < e) {
            int2 e0 = g_edges[i];
            float v0 = __int_as_float(e0.y);
            const float* p0 = src + e0.x * 64;
            gA0 += v0 * p0[lane]; gA1 += v0 * p0[lane + 32];
        }
        float g0 = gA0 + gB0, g1 = gA1 + gB1;

        // ---- GEMV epilogue ----
        float e0v = src[base + lane];
        float e1v = src[base + lane + 32];
        float s0 = e0v + g0, s1 = e1v + g1;
        float z0 = e0v * g0, z1 = e1v * g1;
        float o0 = 0.f, o1 = 0.f;
        #pragma unroll
        for (int k = 0; k < 32; k++) {
            float sv = __shfl_sync(0xffffffffu, s0, k);
            float zv = __shfl_sync(0xffffffffu, z0, k);
            float2 a = wp1[k * 32 + lane];
            float2 b = wp2[k * 32 + lane];
            o0 += sv * a.x + zv * b.x;
            o1 += sv * a.y + zv * b.y;
        }
        #pragma unroll
        for (int k = 0; k < 32; k++) {
            float sv = __shfl_sync(0xffffffffu, s1, k);
            float zv = __shfl_sync(0xffffffffu, z1, k);
            float2 a = wp1[(k + 32) * 32 + lane];
            float2 b = wp2[(k + 32) * 32 + lane];
            o0 += sv * a.x + zv * b.x;
            o1 += sv * a.y + zv * b.y;
        }
        o0 = (o0 > 0.f) ? o0 : 0.01f * o0;
        o1 = (o1 > 0.f) ? o1 : 0.01f * o1;
        if (final_layer) {
            dout[base + lane]      = (g_acc[base + lane]      + o0) * 0.25f;
            dout[base + lane + 32] = (g_acc[base + lane + 32] + o1) * 0.25f;
        } else {
            dst[base + lane]      = o0;
            dst[base + lane + 32] = o1;
            g_acc[base + lane]      += o0;
            g_acc[base + lane + 32] += o1;
        }
    }
}

// ---------------- launch -----------------------------------------------------
extern "C" void kernel_launch(void* const* d_in, const int* in_sizes, int n_in,
                              void* d_out, int out_size) {
    const float* user_emb = (const float*)d_in[0];
    const float* item_emb = (const float*)d_in[1];
    const float* w1       = (const float*)d_in[2];   // [3,64,64]
    const float* w2       = (const float*)d_in[3];   // [3,64,64]
    const float* adj_vals = (const float*)d_in[4];
    const int*   adj_rows = (const int*)d_in[5];
    const int*   adj_cols = (const int*)d_in[6];
    float* dout = (float*)d_out;

    const int NB_SCAN = (N_NODES + 1023) / 1024;     // 147

    // launch slots: 0 init_hist, 1 hist, 2 scan_blocks, 3 scan_sums,
    //               4 add_offsets+scatter... keep k_fused at slot >=5
    k_init_hist<<<(N_NODES * EMB + 255) / 256, 256>>>(user_emb, item_emb, adj_rows);
    k_hist<<<(NNZ + 255) / 256, 256>>>(adj_rows);
    k_scan_blocks<<<NB_SCAN, 1024>>>();
    k_scan_sums<<<1, 256>>>(NB_SCAN);
    k_add_offsets<<<NB_SCAN, 1024>>>();
    k_scatter<<<(NNZ + 255) / 256, 256>>>(adj_rows, adj_cols, adj_vals);

    const int FUSED_BLOCKS = 1184;   // grid-stride; weight staging amortized

    for (int k = 0; k < LAYERS; k++) {
        k_fused<<<FUSED_BLOCKS, 256>>>(w1 + k * EMB * EMB, w2 + k * EMB * EMB,
                                       dout, k & 1, k == LAYERS - 1);
    }
    (void)in_sizes; (void)n_in; (void)out_size;
}

// round 7
// speedup vs baseline: 1.6791x; 1.3646x over previous
#include <cuda_runtime.h>
#include <cuda_bf16.h>

#define USER_NUM 100000
#define ITEM_NUM 50000
#define N_NODES  150000
#define EMB      64
#define LAYERS   3
#define NNZ      2400000

#define TILE 32
#define SROW 68          // padded smem row stride (floats); 68*4=272 B, 16B-aligned

// ---------------- device scratch (static globals: allocation-free) ----------
__device__ float g_egoA[N_NODES * EMB];
__device__ float g_egoB[N_NODES * EMB];
__device__ float g_acc [N_NODES * EMB];
__device__ int   g_rowptr[N_NODES + 1];
__device__ int   g_cursor[N_NODES];
__device__ int   g_counts[N_NODES];
__device__ int   g_bsums[256];
__device__ int2  g_edges[NNZ];           // .x = col, .y = bits(val)

// ---------------- f32x2 helpers ---------------------------------------------
__device__ __forceinline__ unsigned long long f2fma(unsigned long long a,
                                                    unsigned long long b,
                                                    unsigned long long c) {
    unsigned long long d;
    asm("fma.rn.f32x2 %0, %1, %2, %3;" : "=l"(d) : "l"(a), "l"(b), "l"(c));
    return d;
}
__device__ __forceinline__ unsigned long long f2pack(float lo, float hi) {
    unsigned long long d;
    asm("mov.b64 %0, {%1, %2};" : "=l"(d) : "r"(__float_as_uint(lo)), "r"(__float_as_uint(hi)));
    return d;
}
__device__ __forceinline__ void f2unpack(unsigned long long v, float& lo, float& hi) {
    unsigned int a, b;
    asm("mov.b64 {%0, %1}, %2;" : "=r"(a), "=r"(b) : "l"(v));
    lo = __uint_as_float(a); hi = __uint_as_float(b);
}

// ------------- init embeddings, zero counts ---------------------------------
__global__ void k_init(const float* __restrict__ u, const float* __restrict__ it) {
    int i = blockIdx.x * blockDim.x + threadIdx.x;
    if (i < USER_NUM * EMB) {
        float v = u[i];
        g_egoA[i] = v; g_acc[i] = v;
    } else if (i < N_NODES * EMB) {
        float v = it[i - USER_NUM * EMB];
        g_egoA[i] = v; g_acc[i] = v;
    }
    if (i < N_NODES) g_counts[i] = 0;
}

__global__ void k_hist(const int* __restrict__ rows) {
    int i = blockIdx.x * blockDim.x + threadIdx.x;
    if (i < NNZ) atomicAdd(&g_counts[rows[i]], 1);
}

// per-block exclusive scan (1024 elems/block); block totals -> g_bsums
__global__ void k_scan_blocks() {
    __shared__ int sm[1024];
    int idx = blockIdx.x * 1024 + threadIdx.x;
    int v = (idx < N_NODES) ? g_counts[idx] : 0;
    sm[threadIdx.x] = v;
    __syncthreads();
    #pragma unroll
    for (int off = 1; off < 1024; off <<= 1) {
        int t = (threadIdx.x >= off) ? sm[threadIdx.x - off] : 0;
        __syncthreads();
        sm[threadIdx.x] += t;
        __syncthreads();
    }
    if (idx < N_NODES) g_rowptr[idx] = sm[threadIdx.x] - v;   // exclusive
    if (threadIdx.x == 1023) g_bsums[blockIdx.x] = sm[1023];
}

__global__ void k_scan_sums(int nb) {
    __shared__ int sm[256];
    int v = (threadIdx.x < nb) ? g_bsums[threadIdx.x] : 0;
    sm[threadIdx.x] = v;
    __syncthreads();
    #pragma unroll
    for (int off = 1; off < 256; off <<= 1) {
        int t = (threadIdx.x >= off) ? sm[threadIdx.x - off] : 0;
        __syncthreads();
        sm[threadIdx.x] += t;
        __syncthreads();
    }
    if (threadIdx.x < nb) g_bsums[threadIdx.x] = sm[threadIdx.x] - v;  // exclusive
}

__global__ void k_add_offsets() {
    int idx = blockIdx.x * 1024 + threadIdx.x;
    if (idx < N_NODES) {
        int r = g_rowptr[idx] + g_bsums[blockIdx.x];
        g_rowptr[idx] = r;
        g_cursor[idx] = r;
    }
    if (idx == 0) g_rowptr[N_NODES] = NNZ;
}

__global__ void k_scatter(const int* __restrict__ rows, const int* __restrict__ cols,
                          const float* __restrict__ vals) {
    int i = blockIdx.x * blockDim.x + threadIdx.x;
    if (i < NNZ) {
        int r = rows[i];
        int p = atomicAdd(&g_cursor[r], 1);
        g_edges[p] = make_int2(cols[i], __float_as_int(vals[i]));
    }
}

// ------------- fused layer: tile of 32 rows per block -----------------------
//   phase 1: gather g = (A@src)[row]; stage S = src+g, Z = src*g in smem
//   phase 2: O = S@w1 + Z@w2 (register-blocked, f32x2), lrelu, acc/mean
__global__ void __launch_bounds__(256) k_fused(const float* __restrict__ w1,
                                               const float* __restrict__ w2,
                                               float* __restrict__ dout,
                                               int parity, int final_layer) {
    __shared__ __align__(16) float sS[TILE * SROW];
    __shared__ __align__(16) float sZ[TILE * SROW];

    const float* __restrict__ src = parity ? g_egoB : g_egoA;
    float* __restrict__ dst       = parity ? g_egoA : g_egoB;

    int tid  = threadIdx.x;
    int lane = tid & 31;
    int warp = tid >> 5;
    const int ntiles = (N_NODES + TILE - 1) / TILE;

    for (int t = blockIdx.x; t < ntiles; t += gridDim.x) {
        int row0 = t * TILE;

        // ---- phase 1: gather (8 warps x 4 rows) ----
        #pragma unroll
        for (int rr = 0; rr < 4; rr++) {
            int lr  = warp * 4 + rr;
            int row = row0 + lr;
            if (row < N_NODES) {
                int s = g_rowptr[row], e = g_rowptr[row + 1];
                float g0 = 0.f, g1 = 0.f, h0 = 0.f, h1 = 0.f;
                int i = s;
                for (; i + 1 < e; i += 2) {
                    int2 e0 = g_edges[i];
                    int2 e1 = g_edges[i + 1];
                    float v0 = __int_as_float(e0.y);
                    float v1 = __int_as_float(e1.y);
                    const float* p0 = src + e0.x * 64;
                    const float* p1 = src + e1.x * 64;
                    g0 += v0 * p0[lane]; g1 += v0 * p0[lane + 32];
                    h0 += v1 * p1[lane]; h1 += v1 * p1[lane + 32];
                }
                if (i < e) {
                    int2 e0 = g_edges[i];
                    float v0 = __int_as_float(e0.y);
                    const float* p0 = src + e0.x * 64;
                    g0 += v0 * p0[lane]; g1 += v0 * p0[lane + 32];
                }
                g0 += h0; g1 += h1;
                float e0v = src[row * 64 + lane];
                float e1v = src[row * 64 + lane + 32];
                sS[lr * SROW + lane]      = e0v + g0;
                sS[lr * SROW + lane + 32] = e1v + g1;
                sZ[lr * SROW + lane]      = e0v * g0;
                sZ[lr * SROW + lane + 32] = e1v * g1;
            } else {
                sS[lr * SROW + lane] = 0.f; sS[lr * SROW + lane + 32] = 0.f;
                sZ[lr * SROW + lane] = 0.f; sZ[lr * SROW + lane + 32] = 0.f;
            }
        }
        __syncthreads();

        // ---- phase 2: GEMM, thread = 2 rows x 4 cols ----
        int rg = tid >> 4;          // 0..15 -> rows 2rg, 2rg+1
        int cg = tid & 15;          // cols 4cg..4cg+3
        int r0 = 2 * rg, r1 = r0 + 1;
        unsigned long long acc00 = 0ull, acc01 = 0ull, acc10 = 0ull, acc11 = 0ull;

        #pragma unroll
        for (int k = 0; k < 64; k += 4) {
            float4 sv0 = *(const float4*)&sS[r0 * SROW + k];
            float4 sv1 = *(const float4*)&sS[r1 * SROW + k];
            float4 zv0 = *(const float4*)&sZ[r0 * SROW + k];
            float4 zv1 = *(const float4*)&sZ[r1 * SROW + k];
            const float* s0p = (const float*)&sv0;
            const float* s1p = (const float*)&sv1;
            const float* z0p = (const float*)&zv0;
            const float* z1p = (const float*)&zv1;
            #pragma unroll
            for (int kk = 0; kk < 4; kk++) {
                float4 a = __ldg((const float4*)&w1[(k + kk) * 64 + 4 * cg]);
                float4 b = __ldg((const float4*)&w2[(k + kk) * 64 + 4 * cg]);
                unsigned long long a01 = f2pack(a.x, a.y);
                unsigned long long a23 = f2pack(a.z, a.w);
                unsigned long long b01 = f2pack(b.x, b.y);
                unsigned long long b23 = f2pack(b.z, b.w);
                unsigned long long s0d = f2pack(s0p[kk], s0p[kk]);
                unsigned long long s1d = f2pack(s1p[kk], s1p[kk]);
                unsigned long long z0d = f2pack(z0p[kk], z0p[kk]);
                unsigned long long z1d = f2pack(z1p[kk], z1p[kk]);
                acc00 = f2fma(s0d, a01, acc00);
                acc00 = f2fma(z0d, b01, acc00);
                acc01 = f2fma(s0d, a23, acc01);
                acc01 = f2fma(z0d, b23, acc01);
                acc10 = f2fma(s1d, a01, acc10);
                acc10 = f2fma(z1d, b01, acc10);
                acc11 = f2fma(s1d, a23, acc11);
                acc11 = f2fma(z1d, b23, acc11);
            }
        }

        // ---- epilogue ----
        float o[2][4];
        f2unpack(acc00, o[0][0], o[0][1]);
        f2unpack(acc01, o[0][2], o[0][3]);
        f2unpack(acc10, o[1][0], o[1][1]);
        f2unpack(acc11, o[1][2], o[1][3]);
        #pragma unroll
        for (int r = 0; r < 2; r++) {
            #pragma unroll
            for (int c = 0; c < 4; c++) {
                float v = o[r][c];
                o[r][c] = (v > 0.f) ? v : 0.01f * v;
            }
        }
        #pragma unroll
        for (int r = 0; r < 2; r++) {
            int row = row0 + r0 + r;
            if (row < N_NODES) {
                int base = row * 64 + 4 * cg;
                float4 ov = make_float4(o[r][0], o[r][1], o[r][2], o[r][3]);
                if (final_layer) {
                    float4 ac = *(const float4*)&g_acc[base];
                    float4 res;
                    res.x = (ac.x + ov.x) * 0.25f;
                    res.y = (ac.y + ov.y) * 0.25f;
                    res.z = (ac.z + ov.z) * 0.25f;
                    res.w = (ac.w + ov.w) * 0.25f;
                    *(float4*)&dout[base] = res;
                } else {
                    *(float4*)&dst[base] = ov;
                    float4 ac = *(const float4*)&g_acc[base];
                    ac.x += ov.x; ac.y += ov.y; ac.z += ov.z; ac.w += ov.w;
                    *(float4*)&g_acc[base] = ac;
                }
            }
        }
        __syncthreads();   // protect sS/sZ before next tile
    }
}

// ---------------- launch -----------------------------------------------------
extern "C" void kernel_launch(void* const* d_in, const int* in_sizes, int n_in,
                              void* d_out, int out_size) {
    const float* user_emb = (const float*)d_in[0];
    const float* item_emb = (const float*)d_in[1];
    const float* w1       = (const float*)d_in[2];   // [3,64,64]
    const float* w2       = (const float*)d_in[3];   // [3,64,64]
    const float* adj_vals = (const float*)d_in[4];
    const int*   adj_rows = (const int*)d_in[5];
    const int*   adj_cols = (const int*)d_in[6];
    float* dout = (float*)d_out;

    const int NB_SCAN = (N_NODES + 1023) / 1024;     // 147

    k_init<<<(N_NODES * EMB + 255) / 256, 256>>>(user_emb, item_emb);
    k_hist<<<(NNZ + 255) / 256, 256>>>(adj_rows);
    k_scan_blocks<<<NB_SCAN, 1024>>>();
    k_scan_sums<<<1, 256>>>(NB_SCAN);
    k_add_offsets<<<NB_SCAN, 1024>>>();
    k_scatter<<<(NNZ + 255) / 256, 256>>>(adj_rows, adj_cols, adj_vals);

    const int FUSED_BLOCKS = 1184;   // grid-stride over 4688 tiles

    for (int k = 0; k < LAYERS; k++) {
        k_fused<<<FUSED_BLOCKS, 256>>>(w1 + k * EMB * EMB, w2 + k * EMB * EMB,
                                       dout, k & 1, k == LAYERS - 1);
    }
    (void)in_sizes; (void)n_in; (void)out_size;
}